// round 13
// baseline (speedup 1.0000x reference)
#include <cuda_runtime.h>
#include <cuda_fp16.h>
#include <cuda_bf16.h>

#define N_SPARSE 20
#define N_VARLEN 3
#define SEQ_LEN  50
#define VOCAB    100000
#define N_DENSE  13
#define VAR_TOT  (N_VARLEN * SEQ_LEN)   // 150
#define VAR_2ROW (2 * VAR_TOT)          // 300

// fp16 vocab slice [0, S_SLICE) of the 3 varlen tables in smem.
// 3 * 37376 * 2 = 224256 B <= 232448 B (sm_103a max dynamic smem). 1 CTA/SM.
#define S_SLICE     37376
#define SLICE_BYTES (N_VARLEN * S_SLICE * 2)

#define GRID_CTAS   152     // one persistent CTA per SM
#define THREADS     512     // 16 warps/SM (smem-limited to 1 CTA)
#define TOT_WARPS   (GRID_CTAS * (THREADS / 32))   // 2432

struct PairIdx {
    int   sid0, sid1;   // sparse ids (lane < 20), else -1
    int   vid[10];      // 300 varlen ids of the row pair, lane + 32*i
    float dx0, dx1;     // dense_x elements (lane < 13), else 0
};

__device__ __forceinline__ void load_pair_idx(
    int r0, int lane,
    const int*   __restrict__ sparse_ids,
    const int*   __restrict__ varlen_ids,
    const float* __restrict__ dense_x,
    PairIdx& p)
{
    const int r1 = r0 + 1;
    p.sid0 = (lane < N_SPARSE) ? __ldg(sparse_ids + (long)r0 * N_SPARSE + lane) : -1;
    p.sid1 = (lane < N_SPARSE) ? __ldg(sparse_ids + (long)r1 * N_SPARSE + lane) : -1;

    const int* vbase = varlen_ids + (long)r0 * VAR_TOT;   // 300 contiguous ints
    #pragma unroll
    for (int i = 0; i < 9; i++)
        p.vid[i] = __ldg(vbase + lane + i * 32);
    p.vid[9] = (lane + 288 < VAR_2ROW) ? __ldg(vbase + lane + 288) : 0;

    p.dx0 = (lane < N_DENSE) ? __ldg(dense_x + (long)r0 * N_DENSE + lane) : 0.0f;
    p.dx1 = (lane < N_DENSE) ? __ldg(dense_x + (long)r1 * N_DENSE + lane) : 0.0f;
}

__global__ __launch_bounds__(THREADS, 1) void linear_logit_kernel(
    const int*   __restrict__ sparse_ids,     // [B, 20]
    const int*   __restrict__ varlen_ids,     // [B, 3, 50]
    const float* __restrict__ dense_x,        // [B, 13]
    const float* __restrict__ sparse_tables,  // [20, 100000]
    const float* __restrict__ varlen_tables,  // [3, 100000]
    const float* __restrict__ dense_w,        // [13]
    float*       __restrict__ out,            // [B]
    int B)
{
    extern __shared__ __half s_h[];           // [3][S_SLICE]

    // ---- Prologue: build fp16 slice of varlen tables (coalesced float2 -> half2) ----
    #pragma unroll
    for (int f = 0; f < N_VARLEN; f++) {
        const float2* src = (const float2*)(varlen_tables + (long)f * VOCAB);
        __half2*      dst = (__half2*)(s_h + f * S_SLICE);
        for (int i = threadIdx.x; i < S_SLICE / 2; i += THREADS) {
            float2 v = __ldg(src + i);
            dst[i] = __floats2half2_rn(v.x, v.y);
        }
    }
    __syncthreads();

    const int lane  = threadIdx.x & 31;
    const int gwarp = blockIdx.x * (THREADS / 32) + (threadIdx.x >> 5);
    const int npairs = B >> 1;

    const float dw = (lane < N_DENSE) ? __ldg(dense_w + lane) : 0.0f;

    int pair = gwarp;
    if (pair >= npairs) return;

    // Pipeline prologue: prefetch first pair's indices.
    PairIdx cur;
    load_pair_idx(pair * 2, lane, sparse_ids, varlen_ids, dense_x, cur);

    while (pair < npairs) {
        const int npair = pair + TOT_WARPS;

        // ---- Prefetch next pair's indices before current gathers ----
        PairIdx nxt;
        if (npair < npairs)
            load_pair_idx(npair * 2, lane, sparse_ids, varlen_ids, dense_x, nxt);

        const int r0 = pair * 2, r1 = r0 + 1;
        float acc0 = cur.dx0 * dw;
        float acc1 = cur.dx1 * dw;

        // ---- Sparse gathers: L2-resident, divergent LDG ----
        if (cur.sid0 >= 0) acc0 += __ldg(sparse_tables + lane * VOCAB + cur.sid0);
        if (cur.sid1 >= 0) acc1 += __ldg(sparse_tables + lane * VOCAB + cur.sid1);

        // ---- Varlen gathers: 37.4% served by smem fp16 slice, rest LDG ----
        #pragma unroll
        for (int i = 0; i < 10; i++) {
            const int c = lane + i * 32;                  // 0..319
            const bool live = (i < 9 || c < VAR_2ROW) && (cur.vid[i] != 0);
            if (live) {
                const int f = (c / SEQ_LEN) % N_VARLEN;   // folds for most i
                float v;
                if (cur.vid[i] < S_SLICE)
                    v = __half2float(s_h[f * S_SLICE + cur.vid[i]]);
                else
                    v = __ldg(varlen_tables + f * VOCAB + cur.vid[i]);
                if (i < 4)       acc0 += v;
                else if (i > 4)  acc1 += v;
                else { if (c < VAR_TOT) acc0 += v; else acc1 += v; }
            }
        }

        // ---- Two interleaved warp reductions ----
        #pragma unroll
        for (int off = 16; off; off >>= 1) {
            acc0 += __shfl_down_sync(0xffffffffu, acc0, off);
            acc1 += __shfl_down_sync(0xffffffffu, acc1, off);
        }
        if (lane == 0) {
            out[r0] = acc0;
            out[r1] = acc1;
        }

        pair = npair;
        cur  = nxt;
    }
}

extern "C" void kernel_launch(void* const* d_in, const int* in_sizes, int n_in,
                              void* d_out, int out_size)
{
    const int*   sparse_ids    = (const int*)  d_in[0];
    const int*   varlen_ids    = (const int*)  d_in[1];
    const float* dense_x       = (const float*)d_in[2];
    const float* sparse_tables = (const float*)d_in[3];
    const float* varlen_tables = (const float*)d_in[4];
    const float* dense_w       = (const float*)d_in[5];
    float*       out           = (float*)d_out;

    const int B = in_sizes[0] / N_SPARSE;     // 65536

    cudaFuncSetAttribute(linear_logit_kernel,
                         cudaFuncAttributeMaxDynamicSharedMemorySize,
                         SLICE_BYTES);

    linear_logit_kernel<<<GRID_CTAS, THREADS, SLICE_BYTES>>>(
        sparse_ids, varlen_ids, dense_x,
        sparse_tables, varlen_tables, dense_w,
        out, B);
}

// round 15
// speedup vs baseline: 1.0570x; 1.0570x over previous
#include <cuda_runtime.h>
#include <cuda_fp16.h>
#include <cuda_bf16.h>

#define N_SPARSE 20
#define N_VARLEN 3
#define SEQ_LEN  50
#define VOCAB    100000
#define N_DENSE  13
#define VAR_TOT  (N_VARLEN * SEQ_LEN)   // 150
#define VAR_2ROW (2 * VAR_TOT)          // 300

// fp16 vocab slice [0, S_SLICE) of the 3 varlen tables in smem.
// 3 * 36352 * 2 = 218112 B (<= 232448 max dynamic smem). 1 CTA/SM.
#define S_SLICE     36352
#define SLICE_BYTES (N_VARLEN * S_SLICE * 2)

#define GRID_CTAS   152
#define THREADS     640                               // 20 warps/SM
#define TOT_WARPS   (GRID_CTAS * (THREADS / 32))      // 3040

struct PairIdx {
    int   sid0, sid1;    // sparse ids (lane < 20), else -1
    int   vid[10];       // 300 varlen ids of the row pair, lane + 32*i
    float dx0, dx1;      // dense_x elements (lane < 13), else 0
};

struct PairVal {
    float s0, s1;        // sparse gather results
    float v[10];         // varlen gather results (0 for dead lanes)
    float dx0, dx1;      // dense carried through
};

// Predicated index load; 'valid' kills all loads for out-of-range pairs.
__device__ __forceinline__ void load_pair_idx(
    bool valid, int r0, int lane,
    const int*   __restrict__ sparse_ids,
    const int*   __restrict__ varlen_ids,
    const float* __restrict__ dense_x,
    PairIdx& p)
{
    const bool ls = valid && (lane < N_SPARSE);
    p.sid0 = ls ? __ldg(sparse_ids + (long)r0 * N_SPARSE + lane)       : -1;
    p.sid1 = ls ? __ldg(sparse_ids + (long)(r0+1) * N_SPARSE + lane)   : -1;

    const int* vbase = varlen_ids + (long)r0 * VAR_TOT;   // 300 contiguous ints
    #pragma unroll
    for (int i = 0; i < 9; i++)
        p.vid[i] = valid ? __ldg(vbase + lane + i * 32) : 0;
    p.vid[9] = (valid && lane + 288 < VAR_2ROW) ? __ldg(vbase + lane + 288) : 0;

    const bool ld = valid && (lane < N_DENSE);
    p.dx0 = ld ? __ldg(dense_x + (long)r0 * N_DENSE + lane)     : 0.0f;
    p.dx1 = ld ? __ldg(dense_x + (long)(r0+1) * N_DENSE + lane) : 0.0f;
}

// Issue all gathers for a pair into a value buffer. NO accumulation here —
// consumers live one pipeline stage later, so these loads' latency is hidden.
__device__ __forceinline__ void gather_pair(
    const PairIdx& p, int lane,
    const float* __restrict__ sparse_tables,
    const float* __restrict__ varlen_tables,
    const __half* __restrict__ s_h,
    PairVal& v)
{
    v.s0 = (p.sid0 >= 0) ? __ldg(sparse_tables + lane * VOCAB + p.sid0) : 0.0f;
    v.s1 = (p.sid1 >= 0) ? __ldg(sparse_tables + lane * VOCAB + p.sid1) : 0.0f;

    #pragma unroll
    for (int i = 0; i < 10; i++) {
        const int c = lane + i * 32;                   // 0..319
        const bool live = (i < 9 || c < VAR_2ROW) && (p.vid[i] != 0);
        float x = 0.0f;
        if (live) {
            const int f = (c / SEQ_LEN) % N_VARLEN;    // folds except i=1,4,7
            if (p.vid[i] < S_SLICE)
                x = __half2float(s_h[f * S_SLICE + p.vid[i]]);
            else
                x = __ldg(varlen_tables + f * VOCAB + p.vid[i]);
        }
        v.v[i] = x;
    }
    v.dx0 = p.dx0;
    v.dx1 = p.dx1;
}

__device__ __forceinline__ void accumulate_store(
    const PairVal& v, int r0, int lane, float dw,
    float* __restrict__ out)
{
    float acc0 = v.dx0 * dw + v.s0;
    float acc1 = v.dx1 * dw + v.s1;

    #pragma unroll
    for (int i = 0; i < 10; i++) {
        const int c = lane + i * 32;
        if (i < 4)       acc0 += v.v[i];
        else if (i > 4)  acc1 += v.v[i];
        else { if (c < VAR_TOT) acc0 += v.v[i]; else acc1 += v.v[i]; }
    }

    #pragma unroll
    for (int off = 16; off; off >>= 1) {
        acc0 += __shfl_down_sync(0xffffffffu, acc0, off);
        acc1 += __shfl_down_sync(0xffffffffu, acc1, off);
    }
    if (lane == 0) {
        out[r0]     = acc0;
        out[r0 + 1] = acc1;
    }
}

__global__ __launch_bounds__(THREADS, 1) void linear_logit_kernel(
    const int*   __restrict__ sparse_ids,     // [B, 20]
    const int*   __restrict__ varlen_ids,     // [B, 3, 50]
    const float* __restrict__ dense_x,        // [B, 13]
    const float* __restrict__ sparse_tables,  // [20, 100000]
    const float* __restrict__ varlen_tables,  // [3, 100000]
    const float* __restrict__ dense_w,        // [13]
    float*       __restrict__ out,            // [B]
    int B)
{
    extern __shared__ __half s_h[];           // [3][S_SLICE]

    // ---- Prologue: build fp16 slice (coalesced float2 -> half2) ----
    #pragma unroll
    for (int f = 0; f < N_VARLEN; f++) {
        const float2* src = (const float2*)(varlen_tables + (long)f * VOCAB);
        __half2*      dst = (__half2*)(s_h + f * S_SLICE);
        for (int i = threadIdx.x; i < S_SLICE / 2; i += THREADS) {
            float2 t = __ldg(src + i);
            dst[i] = __floats2half2_rn(t.x, t.y);
        }
    }
    __syncthreads();

    const int lane   = threadIdx.x & 31;
    const int gwarp  = blockIdx.x * (THREADS / 32) + (threadIdx.x >> 5);
    const int npairs = B >> 1;

    const float dw = (lane < N_DENSE) ? __ldg(dense_w + lane) : 0.0f;

    int pair = gwarp;
    if (pair >= npairs) return;

    // ---- Pipeline prologue (latency exposed once per warp, amortized) ----
    PairIdx idx_next;
    PairVal val_cur;
    {
        PairIdx idx0;
        load_pair_idx(true, pair * 2, lane, sparse_ids, varlen_ids, dense_x, idx0);
        gather_pair(idx0, lane, sparse_tables, varlen_tables, s_h, val_cur);
    }
    int p1 = pair + TOT_WARPS;
    load_pair_idx(p1 < npairs, p1 * 2, lane, sparse_ids, varlen_ids, dense_x, idx_next);

    // ---- Steady state: 3-stage pipeline, no young scoreboard waits ----
    while (true) {
        const bool has1 = (p1 < npairs);
        const int  p2   = p1 + TOT_WARPS;

        // Stage 1: issue gathers for pair p1 (indices landed last iteration)
        PairVal val_next;
        if (has1)
            gather_pair(idx_next, lane, sparse_tables, varlen_tables, s_h, val_next);

        // Stage 2: issue index loads for pair p2
        PairIdx idx_nn;
        load_pair_idx(p2 < npairs, p2 * 2, lane, sparse_ids, varlen_ids, dense_x, idx_nn);

        // Stage 3: consume pair 'pair' (gathers issued a full iteration ago)
        accumulate_store(val_cur, pair * 2, lane, dw, out);

        if (!has1) break;
        pair     = p1;
        p1       = p2;
        val_cur  = val_next;
        idx_next = idx_nn;
    }
}

extern "C" void kernel_launch(void* const* d_in, const int* in_sizes, int n_in,
                              void* d_out, int out_size)
{
    const int*   sparse_ids    = (const int*)  d_in[0];
    const int*   varlen_ids    = (const int*)  d_in[1];
    const float* dense_x       = (const float*)d_in[2];
    const float* sparse_tables = (const float*)d_in[3];
    const float* varlen_tables = (const float*)d_in[4];
    const float* dense_w       = (const float*)d_in[5];
    float*       out           = (float*)d_out;

    const int B = in_sizes[0] / N_SPARSE;     // 65536

    cudaFuncSetAttribute(linear_logit_kernel,
                         cudaFuncAttributeMaxDynamicSharedMemorySize,
                         SLICE_BYTES);

    linear_logit_kernel<<<GRID_CTAS, THREADS, SLICE_BYTES>>>(
        sparse_ids, varlen_ids, dense_x,
        sparse_tables, varlen_tables, dense_w,
        out, B);
}

// round 16
// speedup vs baseline: 1.5548x; 1.4709x over previous
#include <cuda_runtime.h>
#include <cuda_bf16.h>

#define N_SPARSE 20
#define N_VARLEN 3
#define SEQ_LEN  50
#define VOCAB    100000
#define N_DENSE  13
#define VAR_TOT  (N_VARLEN * SEQ_LEN)   // 150
#define VAR_2ROW (2 * VAR_TOT)          // 300

#define THREADS  256
// 2 rows per warp, 8 warps per CTA -> 16 rows per CTA
#define ROWS_PER_CTA (2 * (THREADS / 32))

__global__ __launch_bounds__(THREADS) void linear_logit_kernel(
    const int*   __restrict__ sparse_ids,     // [B, 20]
    const int*   __restrict__ varlen_ids,     // [B, 3, 50]
    const float* __restrict__ dense_x,        // [B, 13]
    const float* __restrict__ sparse_tables,  // [20, 100000]
    const float* __restrict__ varlen_tables,  // [3, 100000]
    const float* __restrict__ dense_w,        // [13]
    float*       __restrict__ out,            // [B]
    int B)
{
    const int lane  = threadIdx.x & 31;
    const int gwarp = (blockIdx.x * THREADS + threadIdx.x) >> 5;
    const int r0    = gwarp * 2;              // first of the adjacent row pair
    if (r0 >= B) return;
    const int r1 = r0 + 1;                    // B is even (65536); always valid

    // ---------- Phase 1: batch ALL index loads (max front-loaded MLP) ----------
    // Sparse ids: two adjacent 20-int rows.
    const int sid0 = (lane < N_SPARSE) ? __ldg(sparse_ids + (long)r0 * N_SPARSE + lane) : -1;
    const int sid1 = (lane < N_SPARSE) ? __ldg(sparse_ids + (long)r1 * N_SPARSE + lane) : -1;

    // Varlen ids: the pair is one contiguous 300-int block -> 10 coalesced LDGs.
    const int* vbase = varlen_ids + (long)r0 * VAR_TOT;
    int vid[10];
    #pragma unroll
    for (int i = 0; i < 10; i++) {
        const int c = lane + i * 32;
        vid[i] = (c < VAR_2ROW) ? __ldg(vbase + c) : 0;   // only i=9 tail masked
    }

    // Dense.
    const float dw  = (lane < N_DENSE) ? __ldg(dense_w + lane) : 0.0f;
    const float dx0 = (lane < N_DENSE) ? __ldg(dense_x + (long)r0 * N_DENSE + lane) : 0.0f;
    const float dx1 = (lane < N_DENSE) ? __ldg(dense_x + (long)r1 * N_DENSE + lane) : 0.0f;

    float acc0 = dx0 * dw;
    float acc1 = dx1 * dw;

    // ---------- Phase 2: 42 independent gathers (L2-resident tables) ----------
    if (sid0 >= 0) acc0 += __ldg(sparse_tables + lane * VOCAB + sid0);
    if (sid1 >= 0) acc1 += __ldg(sparse_tables + lane * VOCAB + sid1);

    #pragma unroll
    for (int i = 0; i < 10; i++) {
        const int c = lane + i * 32;          // 0..319 over the 2-row block
        const bool live = (i < 9 || c < VAR_2ROW) && (vid[i] != 0);
        if (live) {
            // feature = (c/50) % 3 ; constant-folds for non-straddling i
            const int f = (c / SEQ_LEN) % N_VARLEN;
            const float v = __ldg(varlen_tables + f * VOCAB + vid[i]);
            // which row: c < 150 -> r0, else r1 (compile-time except i=4)
            if (i < 4)       acc0 += v;
            else if (i > 4)  acc1 += v;
            else { if (c < VAR_TOT) acc0 += v; else acc1 += v; }
        }
    }

    // ---------- Phase 3: two independent warp reductions ----------
    #pragma unroll
    for (int off = 16; off; off >>= 1) {
        acc0 += __shfl_down_sync(0xffffffffu, acc0, off);
        acc1 += __shfl_down_sync(0xffffffffu, acc1, off);
    }

    if (lane == 0) {
        out[r0] = acc0;
        out[r1] = acc1;
    }
}

extern "C" void kernel_launch(void* const* d_in, const int* in_sizes, int n_in,
                              void* d_out, int out_size)
{
    const int*   sparse_ids    = (const int*)  d_in[0];
    const int*   varlen_ids    = (const int*)  d_in[1];
    const float* dense_x       = (const float*)d_in[2];
    const float* sparse_tables = (const float*)d_in[3];
    const float* varlen_tables = (const float*)d_in[4];
    const float* dense_w       = (const float*)d_in[5];
    float*       out           = (float*)d_out;

    const int B = in_sizes[0] / N_SPARSE;     // 65536

    // Zero smem -> ask for the full 228KB L1D carveout (more gather hits,
    // shorter average latency, denser eligible-warp pool). Attribute set is
    // host-side and graph-capture-safe; idempotent across calls.
    static bool carveout_set = false;
    if (!carveout_set) {
        cudaFuncSetAttribute(linear_logit_kernel,
                             cudaFuncAttributePreferredSharedMemoryCarveout,
                             0 /* cudaSharedmemCarveoutMaxL1 */);
        carveout_set = true;
    }

    const int blocks = (B + ROWS_PER_CTA - 1) / ROWS_PER_CTA;   // 4096

    linear_logit_kernel<<<blocks, THREADS>>>(
        sparse_ids, varlen_ids, dense_x,
        sparse_tables, varlen_tables, dense_w,
        out, B);
}

// round 17
// speedup vs baseline: 1.6317x; 1.0494x over previous
#include <cuda_runtime.h>
#include <cuda_bf16.h>

#define N_SPARSE 20
#define N_VARLEN 3
#define SEQ_LEN  50
#define VOCAB    100000
#define N_DENSE  13
#define VAR_TOT  (N_VARLEN * SEQ_LEN)   // 150
#define VAR_2ROW (2 * VAR_TOT)          // 300

#define THREADS  256
// 2 rows per warp, 8 warps per CTA -> 16 rows per CTA
#define ROWS_PER_CTA (2 * (THREADS / 32))

__global__ __launch_bounds__(THREADS) void linear_logit_kernel(
    const int*   __restrict__ sparse_ids,     // [B, 20]
    const int*   __restrict__ varlen_ids,     // [B, 3, 50]
    const float* __restrict__ dense_x,        // [B, 13]
    const float* __restrict__ sparse_tables,  // [20, 100000]
    const float* __restrict__ varlen_tables,  // [3, 100000]
    const float* __restrict__ dense_w,        // [13]
    float*       __restrict__ out,            // [B]
    int B)
{
    const int lane  = threadIdx.x & 31;
    const int gwarp = (blockIdx.x * THREADS + threadIdx.x) >> 5;
    const int r0    = gwarp * 2;              // first of the adjacent row pair
    if (r0 >= B) return;
    const int r1 = r0 + 1;                    // B is even (65536); always valid

    // ---------- Phase 1: batch ALL index loads (max front-loaded MLP) ----------
    // Sparse ids: the pair is one contiguous 40-int block. Load coalesced with
    // 2 LDGs (lanes 0..39), then shfl-redistribute so lane l holds
    // sid0 = id[l] (row r0, feature l) and sid1 = id[20+l] (row r1, feature l).
    // ~2.25 lines touched vs ~3.25 for two 20-lane strided loads.
    const int* sbase = sparse_ids + (long)r0 * N_SPARSE;   // 40 contiguous ints
    const int sa = __ldcs(sbase + lane);                               // ids 0..31
    const int sb = (lane < 8) ? __ldcs(sbase + 32 + lane) : 0;          // ids 32..39

    // sid0 for lane l = element l  -> register sa of lane l (identity shuffle)
    const int sid0 = (lane < N_SPARSE) ? sa : -1;
    // sid1 for lane l = element 20+l: l<12 -> sa of lane 20+l ; l>=12 -> sb of lane l-12
    const int from_a = __shfl_sync(0xffffffffu, sa, (lane + 20) & 31);
    const int from_b = __shfl_sync(0xffffffffu, sb, (lane >= 12) ? (lane - 12) : 0);
    const int sid1   = (lane < N_SPARSE) ? ((lane < 12) ? from_a : from_b) : -1;

    // Varlen ids: the pair is one contiguous 300-int block -> 10 coalesced LDGs.
    const int* vbase = varlen_ids + (long)r0 * VAR_TOT;
    int vid[10];
    #pragma unroll
    for (int i = 0; i < 10; i++) {
        const int c = lane + i * 32;
        vid[i] = (c < VAR_2ROW) ? __ldcs(vbase + c) : 0;   // only i=9 tail masked
    }

    // Dense (dense_w is tiny + reused -> keep cached; dense_x streams).
    const float dw  = (lane < N_DENSE) ? __ldg(dense_w + lane) : 0.0f;
    const float dx0 = (lane < N_DENSE) ? __ldcs(dense_x + (long)r0 * N_DENSE + lane) : 0.0f;
    const float dx1 = (lane < N_DENSE) ? __ldcs(dense_x + (long)r1 * N_DENSE + lane) : 0.0f;

    float acc0 = dx0 * dw;
    float acc1 = dx1 * dw;

    // ---------- Phase 2: 42 independent gathers (L2-resident tables) ----------
    if (sid0 >= 0) acc0 += __ldg(sparse_tables + lane * VOCAB + sid0);
    if (sid1 >= 0) acc1 += __ldg(sparse_tables + lane * VOCAB + sid1);

    #pragma unroll
    for (int i = 0; i < 10; i++) {
        const int c = lane + i * 32;          // 0..319 over the 2-row block
        const bool live = (i < 9 || c < VAR_2ROW) && (vid[i] != 0);
        if (live) {
            // feature = (c/50) % 3 ; constant-folds for non-straddling i
            const int f = (c / SEQ_LEN) % N_VARLEN;
            const float v = __ldg(varlen_tables + f * VOCAB + vid[i]);
            // which row: c < 150 -> r0, else r1 (compile-time except i=4)
            if (i < 4)       acc0 += v;
            else if (i > 4)  acc1 += v;
            else { if (c < VAR_TOT) acc0 += v; else acc1 += v; }
        }
    }

    // ---------- Phase 3: two independent warp reductions ----------
    #pragma unroll
    for (int off = 16; off; off >>= 1) {
        acc0 += __shfl_down_sync(0xffffffffu, acc0, off);
        acc1 += __shfl_down_sync(0xffffffffu, acc1, off);
    }

    if (lane == 0) {
        __stcs(out + r0, acc0);               // streaming store: no L1 allocate
        __stcs(out + r1, acc1);
    }
}

extern "C" void kernel_launch(void* const* d_in, const int* in_sizes, int n_in,
                              void* d_out, int out_size)
{
    const int*   sparse_ids    = (const int*)  d_in[0];
    const int*   varlen_ids    = (const int*)  d_in[1];
    const float* dense_x       = (const float*)d_in[2];
    const float* sparse_tables = (const float*)d_in[3];
    const float* varlen_tables = (const float*)d_in[4];
    const float* dense_w       = (const float*)d_in[5];
    float*       out           = (float*)d_out;

    const int B = in_sizes[0] / N_SPARSE;     // 65536

    // Zero smem -> full L1D carveout for the gather-heavy tables.
    static bool carveout_set = false;
    if (!carveout_set) {
        cudaFuncSetAttribute(linear_logit_kernel,
                             cudaFuncAttributePreferredSharedMemoryCarveout,
                             0 /* cudaSharedmemCarveoutMaxL1 */);
        carveout_set = true;
    }

    const int blocks = (B + ROWS_PER_CTA - 1) / ROWS_PER_CTA;   // 4096

    linear_logit_kernel<<<blocks, THREADS>>>(
        sparse_ids, varlen_ids, dense_x,
        sparse_tables, varlen_tables, dense_w,
        out, B);
}